// round 1
// baseline (speedup 1.0000x reference)
#include <cuda_runtime.h>
#include <cstdint>
#include <cstddef>

// ---------------------------------------------------------------------------
// PaLM forward (B=1): 4 layers of MQA attention + SwiGLU FFN, final logits.
// Round-1 baseline: fp32 SIMT tiled GEMMs + small fused kernels.
// ---------------------------------------------------------------------------

#define N_TOK 2048
#define DMODEL 2048
#define NHEAD 16
#define HDIM 128
#define INNER 2048   // NHEAD*HDIM
#define FFI 8192
#define NLAYER 4
#define VOCAB 32000
#define EPS_RMS 1e-5f
#define QSCALE 0.08838834764831845f   // 128^-0.5
#define MASKVAL 1e-10f

// ------------------------- scratch (device globals) ------------------------
__device__ float g_x [N_TOK * DMODEL];
__device__ float g_h [N_TOK * DMODEL];
__device__ float g_q [N_TOK * INNER];
__device__ float g_k [N_TOK * HDIM];
__device__ float g_v [N_TOK * HDIM];
__device__ float g_S [(size_t)NHEAD * N_TOK * N_TOK];  // scores/probs, 256 MB
__device__ float g_ao[N_TOK * INNER];
__device__ float g_f1[N_TOK * FFI];
__device__ float g_f2[N_TOK * FFI];

// ------------------------------ embed gather -------------------------------
__global__ void embed_kernel(const int* __restrict__ tok,
                             const float* __restrict__ emb,
                             float* __restrict__ x) {
    int row = blockIdx.x;
    const float4* src = (const float4*)(emb + (size_t)tok[row] * DMODEL);
    float4* dst = (float4*)(x + (size_t)row * DMODEL);
    for (int d = threadIdx.x; d < DMODEL / 4; d += blockDim.x) dst[d] = src[d];
}

// -------------------------------- rmsnorm ----------------------------------
__global__ void rmsnorm_kernel(const float* __restrict__ x,
                               const float* __restrict__ gamma,
                               float* __restrict__ out) {
    int row = blockIdx.x;
    const float* xr = x + (size_t)row * DMODEL;
    float s = 0.f;
    for (int d = threadIdx.x; d < DMODEL; d += blockDim.x) {
        float v = xr[d];
        s += v * v;
    }
    #pragma unroll
    for (int o = 16; o > 0; o >>= 1) s += __shfl_xor_sync(0xffffffffu, s, o);
    __shared__ float ws[8];
    __shared__ float s_inv;
    int lane = threadIdx.x & 31, wid = threadIdx.x >> 5;
    if (lane == 0) ws[wid] = s;
    __syncthreads();
    if (threadIdx.x == 0) {
        float t = 0.f;
        #pragma unroll
        for (int w = 0; w < 8; w++) t += ws[w];
        s_inv = rsqrtf(t / (float)DMODEL + EPS_RMS);
    }
    __syncthreads();
    float iv = s_inv;
    float* orow = out + (size_t)row * DMODEL;
    for (int d = threadIdx.x; d < DMODEL; d += blockDim.x)
        orow[d] = xr[d] * iv * gamma[d];
}

// ---------------------- softmax with alibi + causal mask -------------------
// Faithful to reference: masked (j > i) entries take pre-softmax value 1e-10
// and DO participate in the softmax. sim = QSCALE*(q.k) + slope_h * j.
__global__ void attn_softmax_kernel(float* __restrict__ S) {
    int i = blockIdx.x, h = blockIdx.y;
    float* row = S + ((size_t)h * N_TOK + i) * N_TOK;
    __shared__ float sm[N_TOK];
    __shared__ float red[8];
    __shared__ float s_max, s_sum;
    int tid = threadIdx.x, lane = tid & 31, wid = tid >> 5;
    float slope = exp2f(-0.5f * (float)(h + 1));

    float mx = -3.4e38f;
    for (int j = tid; j < N_TOK; j += 256) {
        float v = (j <= i) ? (row[j] * QSCALE + slope * (float)j) : MASKVAL;
        sm[j] = v;
        mx = fmaxf(mx, v);
    }
    #pragma unroll
    for (int o = 16; o > 0; o >>= 1) mx = fmaxf(mx, __shfl_xor_sync(0xffffffffu, mx, o));
    if (lane == 0) red[wid] = mx;
    __syncthreads();
    if (tid == 0) {
        float m = red[0];
        #pragma unroll
        for (int w = 1; w < 8; w++) m = fmaxf(m, red[w]);
        s_max = m;
    }
    __syncthreads();
    float m = s_max, s = 0.f;
    for (int j = tid; j < N_TOK; j += 256) {
        float e = expf(sm[j] - m);
        sm[j] = e;
        s += e;
    }
    #pragma unroll
    for (int o = 16; o > 0; o >>= 1) s += __shfl_xor_sync(0xffffffffu, s, o);
    if (lane == 0) red[wid] = s;
    __syncthreads();
    if (tid == 0) {
        float t = 0.f;
        #pragma unroll
        for (int w = 0; w < 8; w++) t += red[w];
        s_sum = t;
    }
    __syncthreads();
    float inv = 1.f / s_sum;
    for (int j = tid; j < N_TOK; j += 256) row[j] = sm[j] * inv;
}

// ------------------------------- SwiGLU gate -------------------------------
__global__ void silu_gate_kernel(float* __restrict__ a, const float* __restrict__ g, int n) {
    int idx = blockIdx.x * blockDim.x + threadIdx.x;
    if (idx < n) {
        float gv = g[idx];
        a[idx] = a[idx] * gv / (1.f + expf(-gv));
    }
}

// ------------------------------ tiled SGEMM --------------------------------
// C[M,N] = A[M,K] * B  (+ R), B row-major [K,N] (NN) or [N,K] (NT, i.e. A*B^T)
// 128x128 blocks, BK=8, 256 threads, 8x8 per-thread microtile, float4 paths.
// All dims are multiples of 128 (N may be 128) and K multiple of 8; no bounds
// checks needed for the shapes used here.
template<bool TRANSB, bool ADDRES>
__global__ __launch_bounds__(256) void sgemm_kernel(
    const float* __restrict__ A, const float* __restrict__ B,
    const float* __restrict__ R, float* __restrict__ C,
    int M, int N, int K, int lda, int ldb, int ldc,
    long long sA, long long sB, long long sC)
{
    A += (size_t)blockIdx.z * (size_t)sA;
    B += (size_t)blockIdx.z * (size_t)sB;
    C += (size_t)blockIdx.z * (size_t)sC;

    const int bm = blockIdx.y * 128, bn = blockIdx.x * 128;
    __shared__ float As[8][128];
    __shared__ float Bs[8][128];

    int tid = threadIdx.x;
    int tx = tid & 15, ty = tid >> 4;
    int lr = tid >> 1, lq = (tid & 1) * 4;   // A (and NT-B) tile loads
    int br = tid >> 5, bc = (tid & 31) * 4;  // NN-B tile loads

    float acc[8][8];
    #pragma unroll
    for (int r = 0; r < 8; r++)
        #pragma unroll
        for (int c = 0; c < 8; c++) acc[r][c] = 0.f;

    const float* Aptr = A + (size_t)(bm + lr) * lda + lq;

    for (int k0 = 0; k0 < K; k0 += 8) {
        float4 av = *(const float4*)(Aptr + k0);
        As[lq + 0][lr] = av.x; As[lq + 1][lr] = av.y;
        As[lq + 2][lr] = av.z; As[lq + 3][lr] = av.w;
        if (!TRANSB) {
            float4 bv = *(const float4*)(B + (size_t)(k0 + br) * ldb + bn + bc);
            *(float4*)(&Bs[br][bc]) = bv;
        } else {
            float4 bv = *(const float4*)(B + (size_t)(bn + lr) * ldb + k0 + lq);
            Bs[lq + 0][lr] = bv.x; Bs[lq + 1][lr] = bv.y;
            Bs[lq + 2][lr] = bv.z; Bs[lq + 3][lr] = bv.w;
        }
        __syncthreads();
        #pragma unroll
        for (int kk = 0; kk < 8; kk++) {
            float4 a0 = *(const float4*)(&As[kk][ty * 8]);
            float4 a1 = *(const float4*)(&As[kk][ty * 8 + 4]);
            float4 b0 = *(const float4*)(&Bs[kk][tx * 8]);
            float4 b1 = *(const float4*)(&Bs[kk][tx * 8 + 4]);
            float a[8] = {a0.x, a0.y, a0.z, a0.w, a1.x, a1.y, a1.z, a1.w};
            float b[8] = {b0.x, b0.y, b0.z, b0.w, b1.x, b1.y, b1.z, b1.w};
            #pragma unroll
            for (int r = 0; r < 8; r++)
                #pragma unroll
                for (int c = 0; c < 8; c++) acc[r][c] += a[r] * b[c];
        }
        __syncthreads();
    }

    #pragma unroll
    for (int r = 0; r < 8; r++) {
        size_t off = (size_t)(bm + ty * 8 + r) * ldc + bn + tx * 8;
        float4 v0 = make_float4(acc[r][0], acc[r][1], acc[r][2], acc[r][3]);
        float4 v1 = make_float4(acc[r][4], acc[r][5], acc[r][6], acc[r][7]);
        if (ADDRES) {
            float4 r0 = *(const float4*)(R + off);
            float4 r1 = *(const float4*)(R + off + 4);
            v0.x += r0.x; v0.y += r0.y; v0.z += r0.z; v0.w += r0.w;
            v1.x += r1.x; v1.y += r1.y; v1.z += r1.z; v1.w += r1.w;
        }
        *(float4*)(C + off) = v0;
        *(float4*)(C + off + 4) = v1;
    }
}

// ------------------------------ host helpers -------------------------------
static inline void run_gemm(bool transB, const float* A, const float* B,
                            const float* R, float* C, int M, int N, int K,
                            int lda, int ldb, int ldc,
                            long long sA = 0, long long sB = 0, long long sC = 0,
                            int batch = 1) {
    dim3 grid(N / 128, M / 128, batch), block(256);
    if (transB)
        sgemm_kernel<true, false><<<grid, block>>>(A, B, nullptr, C, M, N, K, lda, ldb, ldc, sA, sB, sC);
    else if (R)
        sgemm_kernel<false, true><<<grid, block>>>(A, B, R, C, M, N, K, lda, ldb, ldc, sA, sB, sC);
    else
        sgemm_kernel<false, false><<<grid, block>>>(A, B, nullptr, C, M, N, K, lda, ldb, ldc, sA, sB, sC);
}

extern "C" void kernel_launch(void* const* d_in, const int* in_sizes, int n_in,
                              void* d_out, int out_size) {
    const int*   tokens      = (const int*)  d_in[0];
    const float* emb         = (const float*)d_in[1];
    const float* attn_gamma  = (const float*)d_in[2];
    const float* wq          = (const float*)d_in[3];
    const float* wk          = (const float*)d_in[4];
    const float* wv          = (const float*)d_in[5];
    const float* wo          = (const float*)d_in[6];
    const float* ff_gamma    = (const float*)d_in[7];
    const float* wi          = (const float*)d_in[8];
    const float* wg          = (const float*)d_in[9];
    const float* wfo         = (const float*)d_in[10];
    const float* final_gamma = (const float*)d_in[11];

    float *x, *h, *q, *k, *v, *S, *ao, *f1, *f2;
    cudaGetSymbolAddress((void**)&x,  g_x);
    cudaGetSymbolAddress((void**)&h,  g_h);
    cudaGetSymbolAddress((void**)&q,  g_q);
    cudaGetSymbolAddress((void**)&k,  g_k);
    cudaGetSymbolAddress((void**)&v,  g_v);
    cudaGetSymbolAddress((void**)&S,  g_S);
    cudaGetSymbolAddress((void**)&ao, g_ao);
    cudaGetSymbolAddress((void**)&f1, g_f1);
    cudaGetSymbolAddress((void**)&f2, g_f2);

    // x = embedding[tokens]
    embed_kernel<<<N_TOK, 256>>>(tokens, emb, x);

    for (int l = 0; l < NLAYER; l++) {
        const float* wq_l  = wq  + (size_t)l * DMODEL * INNER;
        const float* wk_l  = wk  + (size_t)l * DMODEL * HDIM;
        const float* wv_l  = wv  + (size_t)l * DMODEL * HDIM;
        const float* wo_l  = wo  + (size_t)l * INNER * DMODEL;
        const float* wi_l  = wi  + (size_t)l * DMODEL * FFI;
        const float* wg_l  = wg  + (size_t)l * DMODEL * FFI;
        const float* wfo_l = wfo + (size_t)l * FFI * DMODEL;

        // ---- attention ----
        rmsnorm_kernel<<<N_TOK, 256>>>(x, attn_gamma + (size_t)l * DMODEL, h);
        run_gemm(false, h, wq_l, nullptr, q, N_TOK, INNER, DMODEL, DMODEL, INNER, INNER);
        run_gemm(false, h, wk_l, nullptr, k, N_TOK, HDIM, DMODEL, DMODEL, HDIM, HDIM);
        run_gemm(false, h, wv_l, nullptr, v, N_TOK, HDIM, DMODEL, DMODEL, HDIM, HDIM);

        // S[h] = q_h @ k^T  (batched over heads; q head = column slice of q)
        run_gemm(true, q, k, nullptr, S, N_TOK, N_TOK, HDIM,
                 INNER, HDIM, N_TOK,
                 /*sA=*/HDIM, /*sB=*/0, /*sC=*/(long long)N_TOK * N_TOK, NHEAD);

        attn_softmax_kernel<<<dim3(N_TOK, NHEAD), 256>>>(S);

        // ao[:, h*DH:(h+1)*DH] = P[h] @ v
        run_gemm(false, S, v, nullptr, ao, N_TOK, HDIM, N_TOK,
                 N_TOK, HDIM, INNER,
                 /*sA=*/(long long)N_TOK * N_TOK, /*sB=*/0, /*sC=*/HDIM, NHEAD);

        // x = ao @ wo + x
        run_gemm(false, ao, wo_l, x, x, N_TOK, DMODEL, INNER, INNER, DMODEL, DMODEL);

        // ---- SwiGLU FFN ----
        rmsnorm_kernel<<<N_TOK, 256>>>(x, ff_gamma + (size_t)l * DMODEL, h);
        run_gemm(false, h, wi_l, nullptr, f1, N_TOK, FFI, DMODEL, DMODEL, FFI, FFI);
        run_gemm(false, h, wg_l, nullptr, f2, N_TOK, FFI, DMODEL, DMODEL, FFI, FFI);
        silu_gate_kernel<<<(N_TOK * FFI) / 256, 256>>>(f1, f2, N_TOK * FFI);
        // x = f1 @ wfo + x
        run_gemm(false, f1, wfo_l, x, x, N_TOK, DMODEL, FFI, FFI, DMODEL, DMODEL);
    }

    // final norm + logits = h @ emb^T
    rmsnorm_kernel<<<N_TOK, 256>>>(x, final_gamma, h);
    run_gemm(true, h, emb, nullptr, (float*)d_out, N_TOK, VOCAB, DMODEL,
             DMODEL, DMODEL, VOCAB);
}

// round 6
// speedup vs baseline: 2.5231x; 2.5231x over previous
#include <cuda_runtime.h>
#include <cuda_bf16.h>
#include <cstdint>
#include <cstddef>

#define N_TOK 2048
#define DMODEL 2048
#define NHEAD 16
#define HDIM 128
#define INNER 2048
#define FFI 8192
#define NLAYER 4
#define VOCAB 32000
#define EPS_RMS 1e-5f
#define QSCALE 0.08838834764831845f
#define MASKVAL 1e-10f

typedef __nv_bfloat16 bf16;

// ------------------------------ scratch ------------------------------------
__device__ __align__(256) float g_x [N_TOK * DMODEL];
__device__ __align__(256) float g_S [(size_t)NHEAD * N_TOK * N_TOK];
__device__ __align__(256) float g_v [N_TOK * HDIM];
__device__ __align__(256) float g_f1[N_TOK * FFI];
__device__ __align__(256) float g_f2[N_TOK * FFI];

__device__ __align__(256) bf16 g_hA_h[N_TOK * DMODEL];
__device__ __align__(256) bf16 g_hA_l[N_TOK * DMODEL];
__device__ __align__(256) bf16 g_q_h [N_TOK * INNER];
__device__ __align__(256) bf16 g_q_l [N_TOK * INNER];
__device__ __align__(256) bf16 g_k_h [N_TOK * HDIM];
__device__ __align__(256) bf16 g_k_l [N_TOK * HDIM];
__device__ __align__(256) bf16 g_vT_h[HDIM * N_TOK];
__device__ __align__(256) bf16 g_vT_l[HDIM * N_TOK];
__device__ __align__(256) bf16 g_P_h [(size_t)NHEAD * N_TOK * N_TOK];
__device__ __align__(256) bf16 g_P_l [(size_t)NHEAD * N_TOK * N_TOK];
__device__ __align__(256) bf16 g_ao_h[N_TOK * INNER];
__device__ __align__(256) bf16 g_ao_l[N_TOK * INNER];
__device__ __align__(256) bf16 g_g_h [N_TOK * FFI];
__device__ __align__(256) bf16 g_g_l [N_TOK * FFI];
__device__ __align__(256) bf16 g_wB_h[(size_t)VOCAB * DMODEL];
__device__ __align__(256) bf16 g_wB_l[(size_t)VOCAB * DMODEL];

// ------------------------------ helpers ------------------------------------
__device__ __forceinline__ uint32_t smem_u32(const void* p) {
    uint32_t a;
    asm("{ .reg .u64 t; cvta.to.shared.u64 t, %1; cvt.u32.u64 %0, t; }"
        : "=r"(a) : "l"(p));
    return a;
}
__device__ __forceinline__ uint32_t lds32(uint32_t a) {
    uint32_t v;
    asm volatile("ld.shared.b32 %0, [%1];" : "=r"(v) : "r"(a));
    return v;
}
__device__ __forceinline__ void cp16(uint32_t saddr, const void* gptr) {
    asm volatile("cp.async.cg.shared.global [%0], [%1], 16;"
                 :: "r"(saddr), "l"(gptr));
}
#define CP_COMMIT() asm volatile("cp.async.commit_group;" ::: "memory")
#define CP_WAIT0()  asm volatile("cp.async.wait_group 0;" ::: "memory")
#define CP_WAIT1()  asm volatile("cp.async.wait_group 1;" ::: "memory")

__device__ __forceinline__ void mma16816(float* c, const uint32_t* a, const uint32_t* b) {
    asm volatile(
        "mma.sync.aligned.m16n8k16.row.col.f32.bf16.bf16.f32 "
        "{%0,%1,%2,%3}, {%4,%5,%6,%7}, {%8,%9}, {%0,%1,%2,%3};"
        : "+f"(c[0]), "+f"(c[1]), "+f"(c[2]), "+f"(c[3])
        : "r"(a[0]), "r"(a[1]), "r"(a[2]), "r"(a[3]), "r"(b[0]), "r"(b[1]));
}

__device__ __forceinline__ void split_bf16(float v, unsigned short& h, unsigned short& l) {
    __nv_bfloat16 hb = __float2bfloat16(v);
    float hf = __bfloat162float(hb);
    __nv_bfloat16 lb = __float2bfloat16(v - hf);
    h = *(unsigned short*)&hb;
    l = *(unsigned short*)&lb;
}

// ------------------------------- mma GEMM ----------------------------------
// C[M,N] = (Ah+Al)[M,K] @ (Bh+Bl)^T, B stored [N,K] K-major (split bf16).
// 128x128 CTA tile, BK=32, cp.async double buffer, 8 warps (2x4), warp 64x32.
// EPI: 0 fp32 C; 1 fp32 C + residual R; 2 split bf16 (Ch, Cl).
#define ROWB 80            // padded row stride bytes (32 bf16 + 8 pad)
#define ARR_B (128 * ROWB) // 10240 bytes per tile array
#define STG_B (4 * ARR_B)  // Ah, Al, Bh, Bl
#define GSMEM (2 * STG_B)  // 81920 bytes

template<int EPI>
__global__ __launch_bounds__(256) void mma_gemm_kernel(
    const bf16* __restrict__ Ah, const bf16* __restrict__ Al,
    const bf16* __restrict__ Bh, const bf16* __restrict__ Bl,
    float* __restrict__ C, const float* __restrict__ R,
    bf16* __restrict__ Ch, bf16* __restrict__ Cl,
    int K, int lda, int ldb, int ldc,
    long long sA, long long sB, long long sC)
{
    extern __shared__ char smem[];
    const uint32_t sbase = smem_u32(smem);
    const int tid = threadIdx.x, wid = tid >> 5, lane = tid & 31;
    const int warp_m = wid >> 2, warp_n = wid & 3;
    const int g = lane >> 2, tq = lane & 3;
    const int bm = blockIdx.x * 128, bn = blockIdx.y * 128;

    const long long zC = (long long)blockIdx.z * sC;
    const bf16* pAh = Ah + (long long)blockIdx.z * sA + (size_t)bm * lda;
    const bf16* pAl = Al + (long long)blockIdx.z * sA + (size_t)bm * lda;
    const bf16* pBh = Bh + (long long)blockIdx.z * sB + (size_t)bn * ldb;
    const bf16* pBl = Bl + (long long)blockIdx.z * sB + (size_t)bn * ldb;

    float acc[4][4][4];
    #pragma unroll
    for (int mt = 0; mt < 4; ++mt)
        #pragma unroll
        for (int nt = 0; nt < 4; ++nt)
            #pragma unroll
            for (int i = 0; i < 4; ++i) acc[mt][nt][i] = 0.f;

    const int nch = K >> 5;

    // copy chunk k0 into stage st
    auto copy_chunk = [&](int st, int k0) {
        uint32_t s0 = sbase + st * STG_B;
        #pragma unroll
        for (int it = 0; it < 2; ++it) {
            int i = tid + it * 256;          // 0..511
            int row = i >> 2, seg = i & 3;   // 4 x 16B per 64B row
            uint32_t so = (uint32_t)(row * ROWB + seg * 16);
            size_t ga = (size_t)row * lda + k0 + seg * 8;
            size_t gb = (size_t)row * ldb + k0 + seg * 8;
            cp16(s0 + so,             pAh + ga);
            cp16(s0 + ARR_B + so,     pAl + ga);
            cp16(s0 + 2 * ARR_B + so, pBh + gb);
            cp16(s0 + 3 * ARR_B + so, pBl + gb);
        }
    };

    copy_chunk(0, 0);
    CP_COMMIT();

    for (int c = 0; c < nch; ++c) {
        if (c + 1 < nch) {
            copy_chunk((c + 1) & 1, (c + 1) << 5);
            CP_COMMIT();
            CP_WAIT1();
        } else {
            CP_WAIT0();
        }
        __syncthreads();

        const uint32_t s0 = sbase + (c & 1) * STG_B;
        #pragma unroll
        for (int ks = 0; ks < 2; ++ks) {
            uint32_t ah[4][4], av[4][4], bh[4][2], bv[4][2];
            const int cb = ks * 32 + tq * 4;
            #pragma unroll
            for (int mt = 0; mt < 4; ++mt) {
                uint32_t r0 = s0 + (uint32_t)((warp_m * 64 + mt * 16 + g) * ROWB + cb);
                ah[mt][0] = lds32(r0);
                ah[mt][1] = lds32(r0 + 8 * ROWB);
                ah[mt][2] = lds32(r0 + 16);
                ah[mt][3] = lds32(r0 + 8 * ROWB + 16);
                av[mt][0] = lds32(r0 + ARR_B);
                av[mt][1] = lds32(r0 + ARR_B + 8 * ROWB);
                av[mt][2] = lds32(r0 + ARR_B + 16);
                av[mt][3] = lds32(r0 + ARR_B + 8 * ROWB + 16);
            }
            #pragma unroll
            for (int nt = 0; nt < 4; ++nt) {
                uint32_t rb = s0 + (uint32_t)((warp_n * 32 + nt * 8 + g) * ROWB + cb);
                bh[nt][0] = lds32(rb + 2 * ARR_B);
                bh[nt][1] = lds32(rb + 2 * ARR_B + 16);
                bv[nt][0] = lds32(rb + 3 * ARR_B);
                bv[nt][1] = lds32(rb + 3 * ARR_B + 16);
            }
            #pragma unroll
            for (int mt = 0; mt < 4; ++mt)
                #pragma unroll
                for (int nt = 0; nt < 4; ++nt) {
                    mma16816(acc[mt][nt], ah[mt], bh[nt]);
                    mma16816(acc[mt][nt], ah[mt], bv[nt]);
                    mma16816(acc[mt][nt], av[mt], bh[nt]);
                }
        }
        __syncthreads();
    }

    // ------------------------------ epilogue -------------------------------
    #pragma unroll
    for (int mt = 0; mt < 4; ++mt) {
        #pragma unroll
        for (int nt = 0; nt < 4; ++nt) {
            int row0 = bm + warp_m * 64 + mt * 16 + g;
            int col  = bn + warp_n * 32 + nt * 8 + tq * 2;
            size_t o0 = (size_t)row0 * ldc + col + zC;
            size_t o1 = o0 + (size_t)8 * ldc;
            const float* a = acc[mt][nt];
            if (EPI == 0) {
                *(float2*)(C + o0) = make_float2(a[0], a[1]);
                *(float2*)(C + o1) = make_float2(a[2], a[3]);
            } else if (EPI == 1) {
                float2 r0 = *(const float2*)(R + o0);
                float2 r1 = *(const float2*)(R + o1);
                *(float2*)(C + o0) = make_float2(a[0] + r0.x, a[1] + r0.y);
                *(float2*)(C + o1) = make_float2(a[2] + r1.x, a[3] + r1.y);
            } else {
                unsigned short h0, l0, h1, l1;
                split_bf16(a[0], h0, l0); split_bf16(a[1], h1, l1);
                *(uint32_t*)((unsigned short*)Ch + o0) = (uint32_t)h0 | ((uint32_t)h1 << 16);
                *(uint32_t*)((unsigned short*)Cl + o0) = (uint32_t)l0 | ((uint32_t)l1 << 16);
                split_bf16(a[2], h0, l0); split_bf16(a[3], h1, l1);
                *(uint32_t*)((unsigned short*)Ch + o1) = (uint32_t)h0 | ((uint32_t)h1 << 16);
                *(uint32_t*)((unsigned short*)Cl + o1) = (uint32_t)l0 | ((uint32_t)l1 << 16);
            }
        }
    }
}

// ------------------------------ small kernels ------------------------------
__global__ void embed_kernel(const int* __restrict__ tok, const float* __restrict__ emb,
                             float* __restrict__ x) {
    int row = blockIdx.x;
    const float4* src = (const float4*)(emb + (size_t)tok[row] * DMODEL);
    float4* dst = (float4*)(x + (size_t)row * DMODEL);
    for (int d = threadIdx.x; d < DMODEL / 4; d += blockDim.x) dst[d] = src[d];
}

__global__ void rmsnorm_split_kernel(const float* __restrict__ x,
                                     const float* __restrict__ gamma,
                                     bf16* __restrict__ oh, bf16* __restrict__ ol) {
    int row = blockIdx.x;
    const float* xr = x + (size_t)row * DMODEL;
    float s = 0.f;
    for (int d = threadIdx.x; d < DMODEL; d += blockDim.x) { float v = xr[d]; s += v * v; }
    #pragma unroll
    for (int o = 16; o > 0; o >>= 1) s += __shfl_xor_sync(0xffffffffu, s, o);
    __shared__ float ws[8]; __shared__ float s_inv;
    int lane = threadIdx.x & 31, wid = threadIdx.x >> 5;
    if (lane == 0) ws[wid] = s;
    __syncthreads();
    if (threadIdx.x == 0) {
        float t = 0.f;
        #pragma unroll
        for (int w = 0; w < 8; w++) t += ws[w];
        s_inv = rsqrtf(t / (float)DMODEL + EPS_RMS);
    }
    __syncthreads();
    float iv = s_inv;
    unsigned short* ph = (unsigned short*)(oh + (size_t)row * DMODEL);
    unsigned short* pl = (unsigned short*)(ol + (size_t)row * DMODEL);
    for (int d = threadIdx.x; d < DMODEL; d += blockDim.x) {
        unsigned short h, l;
        split_bf16(xr[d] * iv * gamma[d], h, l);
        ph[d] = h; pl[d] = l;
    }
}

// softmax: sim = QSCALE*s + slope*j (j<=i), else MASKVAL (participates!).
__global__ void softmax_split_kernel(const float* __restrict__ S,
                                     bf16* __restrict__ Ph, bf16* __restrict__ Pl) {
    int i = blockIdx.x, h = blockIdx.y;
    size_t base = ((size_t)h * N_TOK + i) * N_TOK;
    const float* row = S + base;
    unsigned short* oh = (unsigned short*)(Ph + base);
    unsigned short* ol = (unsigned short*)(Pl + base);
    __shared__ float sm[N_TOK];
    __shared__ float red[8];
    __shared__ float s_m, s_z;
    int tid = threadIdx.x, lane = tid & 31, wid = tid >> 5;
    float slope = exp2f(-0.5f * (float)(h + 1));

    float mx = -3.4e38f;
    for (int j = tid; j <= i; j += 256) {
        float v = row[j] * QSCALE + slope * (float)j;
        sm[j] = v;
        mx = fmaxf(mx, v);
    }
    #pragma unroll
    for (int o = 16; o > 0; o >>= 1) mx = fmaxf(mx, __shfl_xor_sync(0xffffffffu, mx, o));
    if (lane == 0) red[wid] = mx;
    __syncthreads();
    if (tid == 0) {
        float m = red[0];
        #pragma unroll
        for (int w = 1; w < 8; w++) m = fmaxf(m, red[w]);
        s_m = fmaxf(m, MASKVAL);
    }
    __syncthreads();
    float m = s_m, s = 0.f;
    for (int j = tid; j <= i; j += 256) {
        float e = __expf(sm[j] - m);
        sm[j] = e;
        s += e;
    }
    #pragma unroll
    for (int o = 16; o > 0; o >>= 1) s += __shfl_xor_sync(0xffffffffu, s, o);
    if (lane == 0) red[wid] = s;
    __syncthreads();
    float emask = __expf(MASKVAL - m);
    if (tid == 0) {
        float t = 0.f;
        #pragma unroll
        for (int w = 0; w < 8; w++) t += red[w];
        s_z = t + (float)(N_TOK - 1 - i) * emask;
    }
    __syncthreads();
    float inv = 1.f / s_z;
    for (int j = tid; j <= i; j += 256) {
        unsigned short hh, ll;
        split_bf16(sm[j] * inv, hh, ll);
        oh[j] = hh; ol[j] = ll;
    }
    unsigned short hm, lm;
    split_bf16(emask * inv, hm, lm);
    for (int j = i + 1 + tid; j < N_TOK; j += 256) { oh[j] = hm; ol[j] = lm; }
}

__global__ void silu_split_kernel(const float* __restrict__ f1, const float* __restrict__ f2,
                                  bf16* __restrict__ oh, bf16* __restrict__ ol, int n) {
    int idx = blockIdx.x * blockDim.x + threadIdx.x;
    if (idx < n) {
        float g = f2[idx];
        float v = f1[idx] * g / (1.f + __expf(-g));
        unsigned short h, l;
        split_bf16(v, h, l);
        ((unsigned short*)oh)[idx] = h;
        ((unsigned short*)ol)[idx] = l;
    }
}

// fp32 [Rr,Cc] -> split bf16 [Cc,Rr]
__global__ void tconv_split_kernel(const float* __restrict__ in,
                                   bf16* __restrict__ oh, bf16* __restrict__ ol,
                                   int Rr, int Cc) {
    __shared__ float t[32][33];
    int x = threadIdx.x, y = threadIdx.y;
    int c0 = blockIdx.x * 32, r0 = blockIdx.y * 32;
    #pragma unroll
    for (int k = 0; k < 4; ++k)
        t[y + 8 * k][x] = in[(size_t)(r0 + y + 8 * k) * Cc + c0 + x];
    __syncthreads();
    #pragma unroll
    for (int k = 0; k < 4; ++k) {
        float v = t[x][y + 8 * k];
        unsigned short h, l;
        split_bf16(v, h, l);
        size_t o = (size_t)(c0 + y + 8 * k) * Rr + r0 + x;
        ((unsigned short*)oh)[o] = h;
        ((unsigned short*)ol)[o] = l;
    }
}

// fp32 -> split bf16, same layout
__global__ void conv_split_kernel(const float* __restrict__ in,
                                  bf16* __restrict__ oh, bf16* __restrict__ ol,
                                  long long n) {
    long long i = ((long long)blockIdx.x * blockDim.x + threadIdx.x) * 4;
    if (i < n) {
        float4 v = *(const float4*)(in + i);
        unsigned short h0, l0, h1, l1, h2, l2, h3, l3;
        split_bf16(v.x, h0, l0); split_bf16(v.y, h1, l1);
        split_bf16(v.z, h2, l2); split_bf16(v.w, h3, l3);
        uint2 hu, lu;
        hu.x = (uint32_t)h0 | ((uint32_t)h1 << 16);
        hu.y = (uint32_t)h2 | ((uint32_t)h3 << 16);
        lu.x = (uint32_t)l0 | ((uint32_t)l1 << 16);
        lu.y = (uint32_t)l2 | ((uint32_t)l3 << 16);
        *(uint2*)((unsigned short*)oh + i) = hu;
        *(uint2*)((unsigned short*)ol + i) = lu;
    }
}

// ------------------------------ host side ----------------------------------
static void tc_gemm(int epi,
                    const bf16* Ah, const bf16* Al, const bf16* Bh, const bf16* Bl,
                    float* C, const float* R, bf16* Ch, bf16* Cl,
                    int M, int N, int K, int lda, int ldb, int ldc,
                    long long sA, long long sB, long long sC, int bz) {
    dim3 g(M / 128, N / 128, bz), b(256);
    if (epi == 0) {
        cudaFuncSetAttribute(mma_gemm_kernel<0>, cudaFuncAttributeMaxDynamicSharedMemorySize, GSMEM);
        mma_gemm_kernel<0><<<g, b, GSMEM>>>(Ah, Al, Bh, Bl, C, R, Ch, Cl, K, lda, ldb, ldc, sA, sB, sC);
    } else if (epi == 1) {
        cudaFuncSetAttribute(mma_gemm_kernel<1>, cudaFuncAttributeMaxDynamicSharedMemorySize, GSMEM);
        mma_gemm_kernel<1><<<g, b, GSMEM>>>(Ah, Al, Bh, Bl, C, R, Ch, Cl, K, lda, ldb, ldc, sA, sB, sC);
    } else {
        cudaFuncSetAttribute(mma_gemm_kernel<2>, cudaFuncAttributeMaxDynamicSharedMemorySize, GSMEM);
        mma_gemm_kernel<2><<<g, b, GSMEM>>>(Ah, Al, Bh, Bl, C, R, Ch, Cl, K, lda, ldb, ldc, sA, sB, sC);
    }
}

static void tconv(const float* in, bf16* oh, bf16* ol, int Rr, int Cc) {
    dim3 g(Cc / 32, Rr / 32), b(32, 8);
    tconv_split_kernel<<<g, b>>>(in, oh, ol, Rr, Cc);
}

extern "C" void kernel_launch(void* const* d_in, const int* in_sizes, int n_in,
                              void* d_out, int out_size) {
    const int*   tokens      = (const int*)  d_in[0];
    const float* emb         = (const float*)d_in[1];
    const float* attn_gamma  = (const float*)d_in[2];
    const float* wq          = (const float*)d_in[3];
    const float* wk          = (const float*)d_in[4];
    const float* wv          = (const float*)d_in[5];
    const float* wo          = (const float*)d_in[6];
    const float* ff_gamma    = (const float*)d_in[7];
    const float* wi          = (const float*)d_in[8];
    const float* wg          = (const float*)d_in[9];
    const float* wfo         = (const float*)d_in[10];
    const float* final_gamma = (const float*)d_in[11];

    float *x, *S, *v, *f1, *f2;
    bf16 *hAh, *hAl, *qh, *ql, *kh, *kl, *vTh, *vTl, *Ph, *Pl, *aoh, *aol, *gh, *gl, *wBh, *wBl;
    cudaGetSymbolAddress((void**)&x,  g_x);
    cudaGetSymbolAddress((void**)&S,  g_S);
    cudaGetSymbolAddress((void**)&v,  g_v);
    cudaGetSymbolAddress((void**)&f1, g_f1);
    cudaGetSymbolAddress((void**)&f2, g_f2);
    cudaGetSymbolAddress((void**)&hAh, g_hA_h); cudaGetSymbolAddress((void**)&hAl, g_hA_l);
    cudaGetSymbolAddress((void**)&qh,  g_q_h);  cudaGetSymbolAddress((void**)&ql,  g_q_l);
    cudaGetSymbolAddress((void**)&kh,  g_k_h);  cudaGetSymbolAddress((void**)&kl,  g_k_l);
    cudaGetSymbolAddress((void**)&vTh, g_vT_h); cudaGetSymbolAddress((void**)&vTl, g_vT_l);
    cudaGetSymbolAddress((void**)&Ph,  g_P_h);  cudaGetSymbolAddress((void**)&Pl,  g_P_l);
    cudaGetSymbolAddress((void**)&aoh, g_ao_h); cudaGetSymbolAddress((void**)&aol, g_ao_l);
    cudaGetSymbolAddress((void**)&gh,  g_g_h);  cudaGetSymbolAddress((void**)&gl,  g_g_l);
    cudaGetSymbolAddress((void**)&wBh, g_wB_h); cudaGetSymbolAddress((void**)&wBl, g_wB_l);

    embed_kernel<<<N_TOK, 256>>>(tokens, emb, x);

    for (int l = 0; l < NLAYER; l++) {
        const float* wq_l  = wq  + (size_t)l * DMODEL * INNER;
        const float* wk_l  = wk  + (size_t)l * DMODEL * HDIM;
        const float* wv_l  = wv  + (size_t)l * DMODEL * HDIM;
        const float* wo_l  = wo  + (size_t)l * INNER * DMODEL;
        const float* wi_l  = wi  + (size_t)l * DMODEL * FFI;
        const float* wg_l  = wg  + (size_t)l * DMODEL * FFI;
        const float* wfo_l = wfo + (size_t)l * FFI * DMODEL;

        // ---- attention ----
        rmsnorm_split_kernel<<<N_TOK, 256>>>(x, attn_gamma + (size_t)l * DMODEL, hAh, hAl);

        tconv(wq_l, wBh, wBl, DMODEL, INNER);   // -> [INNER, DMODEL]
        tc_gemm(2, hAh, hAl, wBh, wBl, nullptr, nullptr, qh, ql,
                N_TOK, INNER, DMODEL, DMODEL, DMODEL, INNER, 0, 0, 0, 1);

        tconv(wk_l, wBh, wBl, DMODEL, HDIM);    // -> [HDIM, DMODEL]
        tc_gemm(2, hAh, hAl, wBh, wBl, nullptr, nullptr, kh, kl,
                N_TOK, HDIM, DMODEL, DMODEL, DMODEL, HDIM, 0, 0, 0, 1);

        tconv(wv_l, wBh, wBl, DMODEL, HDIM);
        tc_gemm(0, hAh, hAl, wBh, wBl, v, nullptr, nullptr, nullptr,
                N_TOK, HDIM, DMODEL, DMODEL, DMODEL, HDIM, 0, 0, 0, 1);
        tconv(v, vTh, vTl, N_TOK, HDIM);        // v [N,HD] -> vT [HD,N]

        // S[h] = q_h @ k^T   (B = k, already [N,K] K-major)
        tc_gemm(0, qh, ql, kh, kl, S, nullptr, nullptr, nullptr,
                N_TOK, N_TOK, HDIM, INNER, HDIM, N_TOK,
                HDIM, 0, (long long)N_TOK * N_TOK, NHEAD);

        softmax_split_kernel<<<dim3(N_TOK, NHEAD), 256>>>(S, Ph, Pl);

        // ao[:, h*DH:] = P[h] @ v   (B = vT [HD, N] K-major over tokens)
        tc_gemm(2, Ph, Pl, vTh, vTl, nullptr, nullptr, aoh, aol,
                N_TOK, HDIM, N_TOK, N_TOK, N_TOK, INNER,
                (long long)N_TOK * N_TOK, 0, HDIM, NHEAD);

        tconv(wo_l, wBh, wBl, INNER, DMODEL);   // -> [DMODEL, INNER]
        tc_gemm(1, aoh, aol, wBh, wBl, x, x, nullptr, nullptr,
                N_TOK, DMODEL, INNER, INNER, INNER, DMODEL, 0, 0, 0, 1);

        // ---- SwiGLU FFN ----
        rmsnorm_split_kernel<<<N_TOK, 256>>>(x, ff_gamma + (size_t)l * DMODEL, hAh, hAl);

        tconv(wi_l, wBh, wBl, DMODEL, FFI);     // -> [FFI, DMODEL]
        tc_gemm(0, hAh, hAl, wBh, wBl, f1, nullptr, nullptr, nullptr,
                N_TOK, FFI, DMODEL, DMODEL, DMODEL, FFI, 0, 0, 0, 1);
        tconv(wg_l, wBh, wBl, DMODEL, FFI);
        tc_gemm(0, hAh, hAl, wBh, wBl, f2, nullptr, nullptr, nullptr,
                N_TOK, FFI, DMODEL, DMODEL, DMODEL, FFI, 0, 0, 0, 1);

        silu_split_kernel<<<(N_TOK * FFI) / 256, 256>>>(f1, f2, gh, gl, N_TOK * FFI);

        tconv(wfo_l, wBh, wBl, FFI, DMODEL);    // -> [DMODEL, FFI]
        tc_gemm(1, gh, gl, wBh, wBl, x, x, nullptr, nullptr,
                N_TOK, DMODEL, FFI, FFI, FFI, DMODEL, 0, 0, 0, 1);
    }

    // final norm + logits = h @ emb^T   (emb already [VOCAB, DMODEL] K-major)
    rmsnorm_split_kernel<<<N_TOK, 256>>>(x, final_gamma, hAh, hAl);
    conv_split_kernel<<<(VOCAB * DMODEL / 4 + 255) / 256, 256>>>(
        emb, wBh, wBl, (long long)VOCAB * DMODEL);
    tc_gemm(0, hAh, hAl, wBh, wBl, (float*)d_out, nullptr, nullptr, nullptr,
            N_TOK, VOCAB, DMODEL, DMODEL, DMODEL, VOCAB, 0, 0, 0, 1);
}